// round 5
// baseline (speedup 1.0000x reference)
#include <cuda_runtime.h>
#include <cuda_bf16.h>

#define BATCH 2
#define NPTS  65536
#define KNN   16
#define DCH   32

// Scratch: coords padded to float4 so gathers are single LDG.128.
__device__ float4 g_coords4[BATCH * NPTS];

__global__ __launch_bounds__(256) void pack_coords_kernel(
    const float* __restrict__ coords)    // (B, N, 3)
{
    int i = blockIdx.x * blockDim.x + threadIdx.x;   // over B*N
    const float* p = coords + (size_t)i * 3;
    g_coords4[i] = make_float4(p[0], p[1], p[2], 0.0f);
}

// One thread handles (b, n, quad-of-4 k's). All 64 output channels written
// as float4 streaming stores (evict-first).
__global__ __launch_bounds__(256) void lse_kernel(
    const float* __restrict__ features,  // (B, D, N, 1)
    const int*   __restrict__ idx,       // (B, N, K)
    const float* __restrict__ w,         // (D, 10)
    const float* __restrict__ bias,      // (D,)
    const float* __restrict__ gamma,
    const float* __restrict__ beta,
    const float* __restrict__ mean,
    const float* __restrict__ var,
    float* __restrict__ out)             // (B, 2D, N, K)
{
    // Folded per-channel params:
    // dot(w, [ext, nb, ext-nb, dist]) = (w0:3 + w6:9)·ext + (w3:6 - w6:9)·nb + w9*dist
    __shared__ float4 s_wa[DCH];  // we.x, we.y, we.z, wn.x
    __shared__ float4 s_wb[DCH];  // wn.y, wn.z, wd,   bias'
    int t = threadIdx.x;
    if (t < DCH) {
        float sc = gamma[t] * rsqrtf(var[t] + 1e-5f);
        const float* wr = w + t * 10;
        float w0 = wr[0], w1 = wr[1], w2 = wr[2], w3 = wr[3], w4 = wr[4];
        float w5 = wr[5], w6 = wr[6], w7 = wr[7], w8 = wr[8], w9 = wr[9];
        s_wa[t] = make_float4((w0 + w6) * sc, (w1 + w7) * sc, (w2 + w8) * sc,
                              (w3 - w6) * sc);
        s_wb[t] = make_float4((w4 - w7) * sc, (w5 - w8) * sc, w9 * sc,
                              (bias[t] - mean[t]) * sc + beta[t]);
    }
    __syncthreads();

    int gid = blockIdx.x * blockDim.x + t;       // 0 .. B*N*4 - 1
    int kq  = gid & 3;                           // which quad of k
    int n   = (gid >> 2) & (NPTS - 1);
    int b   = gid >> 18;                         // gid / (4*N)

    const float4* cb = g_coords4 + (size_t)b * NPTS;
    float4 c = __ldg(cb + n);
    float cx = c.x, cy = c.y, cz = c.z;

    int4 ii = *reinterpret_cast<const int4*>(
        idx + ((size_t)b * NPTS + (size_t)n) * KNN + kq * 4);

    float nx[4], ny[4], nz[4], dist[4];
#pragma unroll
    for (int j = 0; j < 4; j++) {
        int id = (&ii.x)[j];
        float4 nb = __ldg(cb + id);              // single LDG.128 gather
        nx[j] = nb.x; ny[j] = nb.y; nz[j] = nb.z;
        float ddx = cx - nb.x, ddy = cy - nb.y, ddz = cz - nb.z;
        dist[j] = sqrtf(ddx * ddx + ddy * ddy + ddz * ddz);
    }

    const size_t cstride = (size_t)NPTS * KNN;   // per-channel stride in out
    size_t out_base = (size_t)b * 2 * DCH * cstride + (size_t)n * KNN
                      + (size_t)kq * 4;

    // Computed half: y = relu(conv+BN)
#pragma unroll
    for (int o = 0; o < DCH; o++) {
        float4 wa = s_wa[o];
        float4 wb = s_wb[o];
        float base = wb.w + wa.x * cx + wa.y * cy + wa.z * cz;
        float4 r;
        float* rp = &r.x;
#pragma unroll
        for (int j = 0; j < 4; j++) {
            float v = base + wa.w * nx[j] + wb.x * ny[j] + wb.y * nz[j]
                           + wb.z * dist[j];
            rp[j] = fmaxf(v, 0.0f);
        }
        __stcs(reinterpret_cast<float4*>(out + out_base + (size_t)o * cstride),
               r);
    }

    // Broadcast half: features replicated across K
    const float* fb = features + (size_t)b * DCH * NPTS + (size_t)n;
    size_t fout = out_base + (size_t)DCH * cstride;
#pragma unroll
    for (int c2 = 0; c2 < DCH; c2++) {
        float f = __ldg(fb + (size_t)c2 * NPTS);
        __stcs(reinterpret_cast<float4*>(out + fout + (size_t)c2 * cstride),
               make_float4(f, f, f, f));
    }
}

extern "C" void kernel_launch(void* const* d_in, const int* in_sizes, int n_in,
                              void* d_out, int out_size) {
    const float* coords   = (const float*)d_in[0];
    const float* features = (const float*)d_in[1];
    const int*   idx      = (const int*)d_in[2];
    const float* w        = (const float*)d_in[3];
    const float* bias     = (const float*)d_in[4];
    const float* gamma    = (const float*)d_in[5];
    const float* beta     = (const float*)d_in[6];
    const float* mean     = (const float*)d_in[7];
    const float* var      = (const float*)d_in[8];
    float* out = (float*)d_out;

    pack_coords_kernel<<<BATCH * NPTS / 256, 256>>>(coords);

    const int total   = BATCH * NPTS * 4;   // one thread per (b, n, k-quad)
    const int threads = 256;
    const int blocks  = total / threads;    // 2048
    lse_kernel<<<blocks, threads>>>(features, idx, w, bias,
                                    gamma, beta, mean, var, out);
}